// round 2
// baseline (speedup 1.0000x reference)
#include <cuda_runtime.h>

// Lorenz96 RK4 step, batch x 40 fp32.
// Coalesced global access via shared-memory tile staging; RK4 fully in registers.

#define N_STATE 40
#define FORCE_C 8.0f
#define ROWS_PER_BLOCK 128
#define VEC_PER_ROW 10          // 40 floats = 10 float4
#define SMEM_STRIDE 11          // float4 units per row (+1 pad -> 44-float stride, conflict-free)

__device__ __forceinline__ void lorenz_dxdt(const float* __restrict__ x,
                                            float* __restrict__ k) {
#pragma unroll
    for (int i = 0; i < N_STATE; i++) {
        const int ip1 = (i + 1) % N_STATE;
        const int im2 = (i + N_STATE - 2) % N_STATE;
        const int im1 = (i + N_STATE - 1) % N_STATE;
        k[i] = fmaf(x[ip1] - x[im2], x[im1], FORCE_C - x[i]);
    }
}

__global__ __launch_bounds__(ROWS_PER_BLOCK)
void lorenz96_rk4_kernel(const float4* __restrict__ x0,
                         const float* __restrict__ dt_ptr,
                         float4* __restrict__ out,
                         int batch) {
    __shared__ float4 tile[ROWS_PER_BLOCK * SMEM_STRIDE];

    const int tid = threadIdx.x;
    const long long total_vec = (long long)batch * VEC_PER_ROW;
    const long long block_base_vec = (long long)blockIdx.x * (ROWS_PER_BLOCK * VEC_PER_ROW);

    // ---- Stage in: perfectly coalesced LDG.128 ----
#pragma unroll
    for (int kk = 0; kk < VEC_PER_ROW; kk++) {
        const int idx = kk * ROWS_PER_BLOCK + tid;
        const long long g = block_base_vec + idx;
        if (g < total_vec) {
            const int r = idx / VEC_PER_ROW;
            const int c = idx % VEC_PER_ROW;
            tile[r * SMEM_STRIDE + c] = x0[g];
        }
    }
    __syncthreads();

    const int row = blockIdx.x * ROWS_PER_BLOCK + tid;
    const bool active = (row < batch);

    const float dt = __ldg(dt_ptr);
    const float half_dt = 0.5f * dt;
    const float sixth_dt = dt * (1.0f / 6.0f);

    float x[N_STATE], y[N_STATE], k[N_STATE], acc[N_STATE];

    if (active) {
        // ---- Read own row from smem (LDS.128, conflict-free via pad) ----
#pragma unroll
        for (int j = 0; j < VEC_PER_ROW; j++) {
            float4 v = tile[tid * SMEM_STRIDE + j];
            x[4 * j + 0] = v.x;
            x[4 * j + 1] = v.y;
            x[4 * j + 2] = v.z;
            x[4 * j + 3] = v.w;
        }

        // k1
        lorenz_dxdt(x, k);
#pragma unroll
        for (int i = 0; i < N_STATE; i++) {
            acc[i] = k[i];
            y[i] = fmaf(half_dt, k[i], x[i]);
        }
        // k2
        lorenz_dxdt(y, k);
#pragma unroll
        for (int i = 0; i < N_STATE; i++) {
            acc[i] = fmaf(2.0f, k[i], acc[i]);
            y[i] = fmaf(half_dt, k[i], x[i]);
        }
        // k3
        lorenz_dxdt(y, k);
#pragma unroll
        for (int i = 0; i < N_STATE; i++) {
            acc[i] = fmaf(2.0f, k[i], acc[i]);
            y[i] = fmaf(dt, k[i], x[i]);
        }
        // k4
        lorenz_dxdt(y, k);
    }

    __syncthreads();

    if (active) {
        // ---- Write results to smem (STS.128) ----
#pragma unroll
        for (int j = 0; j < VEC_PER_ROW; j++) {
            float4 v;
            v.x = fmaf(sixth_dt, acc[4 * j + 0] + k[4 * j + 0], x[4 * j + 0]);
            v.y = fmaf(sixth_dt, acc[4 * j + 1] + k[4 * j + 1], x[4 * j + 1]);
            v.z = fmaf(sixth_dt, acc[4 * j + 2] + k[4 * j + 2], x[4 * j + 2]);
            v.w = fmaf(sixth_dt, acc[4 * j + 3] + k[4 * j + 3], x[4 * j + 3]);
            tile[tid * SMEM_STRIDE + j] = v;
        }
    }
    __syncthreads();

    // ---- Stage out: perfectly coalesced STG.128 ----
#pragma unroll
    for (int kk = 0; kk < VEC_PER_ROW; kk++) {
        const int idx = kk * ROWS_PER_BLOCK + tid;
        const long long g = block_base_vec + idx;
        if (g < total_vec) {
            const int r = idx / VEC_PER_ROW;
            const int c = idx % VEC_PER_ROW;
            out[g] = tile[r * SMEM_STRIDE + c];
        }
    }
}

extern "C" void kernel_launch(void* const* d_in, const int* in_sizes, int n_in,
                              void* d_out, int out_size) {
    const float4* x0 = (const float4*)d_in[0];
    // d_in[1] is t (unused, autonomous system)
    const float* dt = (const float*)d_in[2];
    float4* out = (float4*)d_out;

    const int batch = in_sizes[0] / N_STATE;
    const int blocks = (batch + ROWS_PER_BLOCK - 1) / ROWS_PER_BLOCK;
    lorenz96_rk4_kernel<<<blocks, ROWS_PER_BLOCK>>>(x0, dt, out, batch);
}

// round 3
// speedup vs baseline: 1.2129x; 1.2129x over previous
#include <cuda_runtime.h>

// Lorenz96 RK4 step, batch x 40 fp32.
// 4 threads per row (10 elements each), halo exchange via warp shuffles.
// Coalesced global I/O via small shared-memory tile.

#define N_STATE 40
#define FORCE_C 8.0f
#define TPB 128
#define TPR 4                       // threads per row
#define EPT 10                      // elements per thread
#define ROWS_PER_BLOCK (TPB / TPR)  // 32
#define PAD 48                      // floats per row in smem (192 B, 16B-aligned)
#define VEC_PER_ROW 10              // float4 per row
#define TILE_VECS (ROWS_PER_BLOCK * VEC_PER_ROW)  // 320

// One RK4 stage: k = dxdt(y); acc (init or +=w*k); ynext = x + c*k.
template <bool FIRST, bool HAS_NEXT>
__device__ __forceinline__ void rk4_stage(const float* __restrict__ y,
                                          float* __restrict__ acc,
                                          const float* __restrict__ x,
                                          float* __restrict__ ynext,
                                          float wacc, float cstep,
                                          int left_lane, int right_lane) {
    // Halos: right neighbor's element 0 (= my i+1 at e=9),
    //        left neighbor's elements 9 (= i-1 at e=0 / i-2 at e=1) and 8 (= i-2 at e=0)
    const unsigned FULL = 0xffffffffu;
    const float hR  = __shfl_sync(FULL, y[0], right_lane);
    const float hL9 = __shfl_sync(FULL, y[9], left_lane);
    const float hL8 = __shfl_sync(FULL, y[8], left_lane);

#pragma unroll
    for (int e = 0; e < EPT; e++) {
        const int ip = (e + 1 < EPT) ? e + 1 : 0;   // safe compile-time index
        const int m1 = (e >= 1) ? e - 1 : 0;
        const int m2 = (e >= 2) ? e - 2 : 0;
        const float yp1 = (e == EPT - 1) ? hR : y[ip];
        const float ym1 = (e == 0) ? hL9 : y[m1];
        const float ym2 = (e == 0) ? hL8 : ((e == 1) ? hL9 : y[m2]);

        const float k = fmaf(yp1 - ym2, ym1, FORCE_C - y[e]);
        if (FIRST)
            acc[e] = k;
        else
            acc[e] = fmaf(wacc, k, acc[e]);
        if (HAS_NEXT)
            ynext[e] = fmaf(cstep, k, x[e]);
    }
}

__global__ __launch_bounds__(TPB, 6)
void lorenz96_rk4_kernel(const float4* __restrict__ x0,
                         const float* __restrict__ dt_ptr,
                         float4* __restrict__ out,
                         int batch) {
    __shared__ float tile[ROWS_PER_BLOCK * PAD];

    const int tid = threadIdx.x;
    const long long total_vec = (long long)batch * VEC_PER_ROW;
    const long long base_vec = (long long)blockIdx.x * TILE_VECS;

    // ---- Stage in: coalesced LDG.128 -> smem ----
#pragma unroll
    for (int it = 0; it < (TILE_VECS + TPB - 1) / TPB; it++) {
        const int idx = it * TPB + tid;
        const long long g = base_vec + idx;
        if (idx < TILE_VECS && g < total_vec) {
            const int r = idx / VEC_PER_ROW;
            const int c = idx % VEC_PER_ROW;
            *reinterpret_cast<float4*>(&tile[r * PAD + c * 4]) = x0[g];
        }
    }
    __syncthreads();

    const int lane = tid & 31;
    const int q = tid & 3;                 // quarter of the row
    const int r_local = tid >> 2;          // row within block
    const int lane_base = lane & ~3;
    const int left_lane  = lane_base | ((q + 3) & 3);
    const int right_lane = lane_base | ((q + 1) & 3);

    const float dt = __ldg(dt_ptr);
    const float half_dt = 0.5f * dt;
    const float sixth_dt = dt * (1.0f / 6.0f);

    // ---- Load my 10 elements ----
    float x[EPT];
#pragma unroll
    for (int e = 0; e < EPT; e++)
        x[e] = tile[r_local * PAD + q * EPT + e];

    float acc[EPT], ya[EPT], yb[EPT];

    // k1: from x, acc = k, ya = x + dt/2 * k
    rk4_stage<true, true>(x, acc, x, ya, 1.0f, half_dt, left_lane, right_lane);
    // k2: from ya, acc += 2k, yb = x + dt/2 * k
    rk4_stage<false, true>(ya, acc, x, yb, 2.0f, half_dt, left_lane, right_lane);
    // k3: from yb, acc += 2k, ya = x + dt * k
    rk4_stage<false, true>(yb, acc, x, ya, 2.0f, dt, left_lane, right_lane);
    // k4: from ya, acc += k
    rk4_stage<false, false>(ya, acc, x, ya, 1.0f, 0.0f, left_lane, right_lane);

    // ---- Write results back to my smem region ----
#pragma unroll
    for (int e = 0; e < EPT; e++)
        tile[r_local * PAD + q * EPT + e] = fmaf(sixth_dt, acc[e], x[e]);
    __syncthreads();

    // ---- Stage out: smem -> coalesced STG.128 ----
#pragma unroll
    for (int it = 0; it < (TILE_VECS + TPB - 1) / TPB; it++) {
        const int idx = it * TPB + tid;
        const long long g = base_vec + idx;
        if (idx < TILE_VECS && g < total_vec) {
            const int r = idx / VEC_PER_ROW;
            const int c = idx % VEC_PER_ROW;
            out[g] = *reinterpret_cast<const float4*>(&tile[r * PAD + c * 4]);
        }
    }
}

extern "C" void kernel_launch(void* const* d_in, const int* in_sizes, int n_in,
                              void* d_out, int out_size) {
    const float4* x0 = (const float4*)d_in[0];
    // d_in[1] is t (unused, autonomous system)
    const float* dt = (const float*)d_in[2];
    float4* out = (float4*)d_out;

    const int batch = in_sizes[0] / N_STATE;
    const int blocks = (batch + ROWS_PER_BLOCK - 1) / ROWS_PER_BLOCK;
    lorenz96_rk4_kernel<<<blocks, TPB>>>(x0, dt, out, batch);
}

// round 4
// speedup vs baseline: 1.2834x; 1.0581x over previous
#include <cuda_runtime.h>

// Lorenz96 RK4 step, batch x 40 fp32.
// 10 threads per row, 4 elements (one aligned float4) each.
// No shared memory: direct coalesced float4 gmem I/O; halos via warp shuffles.
// Each warp: lanes 0-29 = 3 rows of 10 threads; lanes 30,31 idle.

#define N_STATE 40
#define FORCE_C 8.0f
#define TPB 256
#define WARPS_PER_BLOCK (TPB / 32)
#define ROWS_PER_WARP 3

template <bool FIRST, bool HAS_NEXT>
__device__ __forceinline__ void rk4_stage(const float* __restrict__ y,
                                          float* __restrict__ acc,
                                          const float* __restrict__ x,
                                          float* __restrict__ ynext,
                                          float wacc, float cstep,
                                          unsigned mask, int left, int right) {
    // i = 4t+e. Need: left lane's y[2] (i-2 at e=0), left's y[3] (i-1 at e=0, i-2 at e=1),
    // right lane's y[0] (i+1 at e=3).
    const float hL2 = __shfl_sync(mask, y[2], left);
    const float hL3 = __shfl_sync(mask, y[3], left);
    const float hR0 = __shfl_sync(mask, y[0], right);

    float k0 = fmaf(y[1] - hL2, hL3,  FORCE_C - y[0]);
    float k1 = fmaf(y[2] - hL3, y[0], FORCE_C - y[1]);
    float k2 = fmaf(y[3] - y[0], y[1], FORCE_C - y[2]);
    float k3 = fmaf(hR0 - y[1], y[2], FORCE_C - y[3]);

    if (FIRST) {
        acc[0] = k0; acc[1] = k1; acc[2] = k2; acc[3] = k3;
    } else {
        acc[0] = fmaf(wacc, k0, acc[0]);
        acc[1] = fmaf(wacc, k1, acc[1]);
        acc[2] = fmaf(wacc, k2, acc[2]);
        acc[3] = fmaf(wacc, k3, acc[3]);
    }
    if (HAS_NEXT) {
        ynext[0] = fmaf(cstep, k0, x[0]);
        ynext[1] = fmaf(cstep, k1, x[1]);
        ynext[2] = fmaf(cstep, k2, x[2]);
        ynext[3] = fmaf(cstep, k3, x[3]);
    }
}

__global__ __launch_bounds__(TPB)
void lorenz96_rk4_kernel(const float4* __restrict__ x0,
                         const float* __restrict__ dt_ptr,
                         float4* __restrict__ out,
                         int batch) {
    const int lane = threadIdx.x & 31;
    if (lane >= 30) return;   // lanes 30,31 unused (not in any shfl mask)

    const int g = lane / 10;            // row group within warp: 0,1,2
    const int t = lane - g * 10;        // position within row: 0..9

    const long long warp_global =
        (long long)blockIdx.x * WARPS_PER_BLOCK + (threadIdx.x >> 5);
    const long long row = warp_global * ROWS_PER_WARP + g;
    if (row >= batch) return;           // whole 10-lane group exits together

    const unsigned mask = 0x3FFu << (g * 10);
    const int left  = (t == 0) ? lane + 9 : lane - 1;
    const int right = (t == 9) ? lane - 9 : lane + 1;

    const float dt = __ldg(dt_ptr);
    const float half_dt = 0.5f * dt;
    const float sixth_dt = dt * (1.0f / 6.0f);

    // Coalesced load: thread t of row reads float4 #t of that row.
    const float4 v = x0[row * 10 + t];
    float x[4] = {v.x, v.y, v.z, v.w};

    float acc[4], ya[4], yb[4];

    // k1: from x;  acc = k;       ya = x + dt/2 * k
    rk4_stage<true,  true >(x,  acc, x, ya, 1.0f, half_dt, mask, left, right);
    // k2: from ya; acc += 2k;     yb = x + dt/2 * k
    rk4_stage<false, true >(ya, acc, x, yb, 2.0f, half_dt, mask, left, right);
    // k3: from yb; acc += 2k;     ya = x + dt * k
    rk4_stage<false, true >(yb, acc, x, ya, 2.0f, dt,      mask, left, right);
    // k4: from ya; acc += k
    rk4_stage<false, false>(ya, acc, x, yb, 1.0f, 0.0f,    mask, left, right);

    float4 o;
    o.x = fmaf(sixth_dt, acc[0], x[0]);
    o.y = fmaf(sixth_dt, acc[1], x[1]);
    o.z = fmaf(sixth_dt, acc[2], x[2]);
    o.w = fmaf(sixth_dt, acc[3], x[3]);
    out[row * 10 + t] = o;
}

extern "C" void kernel_launch(void* const* d_in, const int* in_sizes, int n_in,
                              void* d_out, int out_size) {
    const float4* x0 = (const float4*)d_in[0];
    // d_in[1] is t (unused, autonomous system)
    const float* dt = (const float*)d_in[2];
    float4* out = (float4*)d_out;

    const int batch = in_sizes[0] / N_STATE;
    const long long rows_per_block = (long long)WARPS_PER_BLOCK * ROWS_PER_WARP;
    const int blocks = (int)((batch + rows_per_block - 1) / rows_per_block);
    lorenz96_rk4_kernel<<<blocks, TPB>>>(x0, dt, out, batch);
}

// round 5
// speedup vs baseline: 1.3427x; 1.0462x over previous
#include <cuda_runtime.h>

// Lorenz96 RK4, batch x 40 fp32.
// Two rows packed per thread via fp32x2 (rows r and r+3 of a 6-row warp tile).
// 10 threads per row-pair, 4 packed elements each; halos via 64-bit shuffles.
// All math in fma.rn.f32x2 (bit-exact lanewise IEEE fp32).

#define N_STATE 40
#define TPB 256
#define WARPS_PER_BLOCK (TPB / 32)
#define ROWS_PER_WARP 6

typedef unsigned long long ull;

__device__ __forceinline__ ull pack2(float lo, float hi) {
    ull r;
    asm("mov.b64 %0, {%1, %2};" : "=l"(r) : "f"(lo), "f"(hi));
    return r;
}
__device__ __forceinline__ void unpack2(ull v, float& lo, float& hi) {
    asm("mov.b64 {%0, %1}, %2;" : "=f"(lo), "=f"(hi) : "l"(v));
}
__device__ __forceinline__ ull fma2(ull a, ull b, ull c) {
    ull d;
    asm("fma.rn.f32x2 %0, %1, %2, %3;" : "=l"(d) : "l"(a), "l"(b), "l"(c));
    return d;
}

#define NEG1_2 0xBF800000BF800000ULL   // (-1, -1)
#define ONE_2  0x3F8000003F800000ULL   // ( 1,  1)
#define TWO_2  0x4000000040000000ULL   // ( 2,  2)
#define F_2    0x4100000041000000ULL   // ( 8,  8)  FORCE

// One RK4 stage on packed pairs. k = (y_{i+1}-y_{i-2})*y_{i-1} + (F - y_i).
template <bool FIRST, bool HAS_NEXT>
__device__ __forceinline__ void stage(const ull* __restrict__ y,
                                      ull* __restrict__ acc,
                                      const ull* __restrict__ x,
                                      ull* __restrict__ yn,
                                      ull W2, ull C2,
                                      unsigned mask, int left, int right) {
    const ull hL2 = __shfl_sync(mask, y[2], left);   // i-2 at e=0
    const ull hL3 = __shfl_sync(mask, y[3], left);   // i-1 at e=0, i-2 at e=1
    const ull hR0 = __shfl_sync(mask, y[0], right);  // i+1 at e=3

    const ull yp1[4] = { y[1], y[2], y[3], hR0 };
    const ull ym1[4] = { hL3,  y[0], y[1], y[2] };
    const ull ym2[4] = { hL2,  hL3,  y[0], y[1] };

#pragma unroll
    for (int e = 0; e < 4; e++) {
        const ull d = fma2(ym2[e], NEG1_2, yp1[e]);   // y_{i+1} - y_{i-2}
        const ull t = fma2(y[e],   NEG1_2, F_2);      // F - y_i
        const ull k = fma2(d, ym1[e], t);
        if (FIRST)
            acc[e] = k;
        else
            acc[e] = fma2(k, W2, acc[e]);
        if (HAS_NEXT)
            yn[e] = fma2(k, C2, x[e]);
    }
}

__global__ __launch_bounds__(TPB)
void lorenz96_rk4_kernel(const float4* __restrict__ x0,
                         const float* __restrict__ dt_ptr,
                         float4* __restrict__ out,
                         int batch) {
    const int lane = threadIdx.x & 31;
    if (lane >= 30) return;                 // lanes 30,31 idle (in no shfl mask)

    const int g = (lane >= 20) ? 2 : (lane >= 10 ? 1 : 0);  // row-pair group
    const int t = lane - g * 10;                            // element chunk 0..9

    const int warp = blockIdx.x * WARPS_PER_BLOCK + (threadIdx.x >> 5);
    const int rowA = warp * ROWS_PER_WARP + g;   // rows (rowA, rowA+3) per group
    if (rowA >= batch) return;                   // uniform within group
    const int rowB = rowA + 3;
    const bool bOK = (rowB < batch);
    const int rB = bOK ? rowB : rowA;            // safe address when clamped

    const unsigned mask = 0x3FFu << (g * 10);
    const int base = g * 10;
    const int left  = (t == 0) ? base + 9 : lane - 1;
    const int right = (t == 9) ? base     : lane + 1;

    const float dt = __ldg(dt_ptr);
    const ull dt2  = pack2(dt, dt);
    const ull hdt2 = pack2(0.5f * dt, 0.5f * dt);
    const float sdt = dt * (1.0f / 6.0f);
    const ull sdt2 = pack2(sdt, sdt);

    // Coalesced loads: group covers 3 consecutive rows per load phase.
    const float4 va = x0[rowA * 10 + t];
    const float4 vb = x0[rB   * 10 + t];

    ull x[4] = { pack2(va.x, vb.x), pack2(va.y, vb.y),
                 pack2(va.z, vb.z), pack2(va.w, vb.w) };

    ull acc[4], ya[4], yb[4];

    // k1: acc = k;       ya = x + dt/2 * k
    stage<true,  true >(x,  acc, x, ya, ONE_2, hdt2, mask, left, right);
    // k2: acc += 2k;     yb = x + dt/2 * k
    stage<false, true >(ya, acc, x, yb, TWO_2, hdt2, mask, left, right);
    // k3: acc += 2k;     ya = x + dt * k
    stage<false, true >(yb, acc, x, ya, TWO_2, dt2,  mask, left, right);
    // k4: acc += k
    stage<false, false>(ya, acc, x, yb, ONE_2, dt2,  mask, left, right);

    // out = x + dt/6 * acc
    float4 oa, ob;
    ull o0 = fma2(acc[0], sdt2, x[0]);
    ull o1 = fma2(acc[1], sdt2, x[1]);
    ull o2 = fma2(acc[2], sdt2, x[2]);
    ull o3 = fma2(acc[3], sdt2, x[3]);
    unpack2(o0, oa.x, ob.x);
    unpack2(o1, oa.y, ob.y);
    unpack2(o2, oa.z, ob.z);
    unpack2(o3, oa.w, ob.w);

    out[rowA * 10 + t] = oa;
    if (bOK) out[rowB * 10 + t] = ob;
}

extern "C" void kernel_launch(void* const* d_in, const int* in_sizes, int n_in,
                              void* d_out, int out_size) {
    const float4* x0 = (const float4*)d_in[0];
    // d_in[1] is t (unused, autonomous system)
    const float* dt = (const float*)d_in[2];
    float4* out = (float4*)d_out;

    const int batch = in_sizes[0] / N_STATE;
    const int rows_per_block = WARPS_PER_BLOCK * ROWS_PER_WARP;  // 48
    const int blocks = (batch + rows_per_block - 1) / rows_per_block;
    lorenz96_rk4_kernel<<<blocks, TPB>>>(x0, dt, out, batch);
}